// round 1
// baseline (speedup 1.0000x reference)
#include <cuda_runtime.h>
#include <cstdint>
#include <cstddef>

#define N_NODES 4096
#define IN_DIM  512
#define OUT_DIM 512
#define HEADS   4
#define DK      128
#define BI      32
#define BJ      32
#define WROW    132   // padded w_s row stride (floats): 132*4B, 16B-aligned, breaks %32 bank pattern
#define AROW    33    // padded adjacency tile row (ints)

// Scratch (device globals: no allocations allowed in kernel_launch)
__device__ float g_Wh[N_NODES * OUT_DIM];
__device__ float g_sl[N_NODES * HEADS];
__device__ float g_sr[N_NODES * HEADS];

typedef unsigned long long ull;

__device__ __forceinline__ ull pk2(float x) {
    ull r; asm("mov.b64 %0, {%1, %1};" : "=l"(r) : "f"(x)); return r;
}
__device__ __forceinline__ void fma2(ull &a, ull b, ull c) {
    // packed fp32x2 FMA (Blackwell): a.lo += b.lo*c.lo ; a.hi += b.hi*c.hi
    asm("fma.rn.f32x2 %0, %1, %2, %0;" : "+l"(a) : "l"(b), "l"(c));
}
__device__ __forceinline__ float2 up2(ull a) {
    float2 f; asm("mov.b64 {%0, %1}, %2;" : "=f"(f.x), "=f"(f.y) : "l"(a)); return f;
}
__device__ __forceinline__ float elu1(float x) {
    return x > 0.f ? x : (__expf(x) - 1.f);
}

// ---------------------------------------------------------------------------
// Kernel 1: Wh = H @ W   (4096x512 @ 512x512, fp32, f32x2 packed FMA)
// ---------------------------------------------------------------------------
__global__ __launch_bounds__(256) void gemm_wh(const float* __restrict__ H,
                                               const float* __restrict__ W) {
    __shared__ float As[16][64];
    __shared__ float Bs[16][64];
    const int t  = threadIdx.x;
    const int m0 = blockIdx.y * 64;
    const int n0 = blockIdx.x * 64;

    const int lm  = t >> 2, lkq = t & 3;    // A-tile load ids
    const int lk  = t >> 4, lnq = t & 15;   // B-tile load ids
    const int ty  = t >> 4, tx  = t & 15;
    const int row0 = ty * 4, col0 = tx * 4;

    ull acc[4][2];
    #pragma unroll
    for (int r = 0; r < 4; ++r) { acc[r][0] = 0ull; acc[r][1] = 0ull; }

    for (int k0 = 0; k0 < IN_DIM; k0 += 16) {
        __syncthreads();
        float4 ha = *(const float4*)(H + (size_t)(m0 + lm) * IN_DIM + k0 + lkq * 4);
        As[lkq * 4 + 0][lm] = ha.x;
        As[lkq * 4 + 1][lm] = ha.y;
        As[lkq * 4 + 2][lm] = ha.z;
        As[lkq * 4 + 3][lm] = ha.w;
        *(float4*)&Bs[lk][lnq * 4] =
            *(const float4*)(W + (size_t)(k0 + lk) * OUT_DIM + n0 + lnq * 4);
        __syncthreads();
        #pragma unroll
        for (int k = 0; k < 16; ++k) {
            float4 av = *(const float4*)&As[k][row0];
            ulonglong2 bb = *(const ulonglong2*)&Bs[k][col0];
            ull am[4] = { pk2(av.x), pk2(av.y), pk2(av.z), pk2(av.w) };
            #pragma unroll
            for (int r = 0; r < 4; ++r) {
                fma2(acc[r][0], am[r], bb.x);
                fma2(acc[r][1], am[r], bb.y);
            }
        }
    }
    #pragma unroll
    for (int r = 0; r < 4; ++r) {
        float2 lo = up2(acc[r][0]);
        float2 hi = up2(acc[r][1]);
        float4 o = make_float4(lo.x, lo.y, hi.x, hi.y);
        *(float4*)(g_Wh + (size_t)(m0 + row0 + r) * OUT_DIM + n0 + col0) = o;
    }
}

// ---------------------------------------------------------------------------
// Kernel 2: sl[i,h] = Wh[i,h,:].a_l[h],  sr likewise
// ---------------------------------------------------------------------------
__global__ __launch_bounds__(128) void slsr_kernel(const float* __restrict__ a_l,
                                                   const float* __restrict__ a_r) {
    const int i    = blockIdx.x;
    const int h    = threadIdx.x >> 5;
    const int lane = threadIdx.x & 31;
    const float* row = g_Wh + (size_t)i * OUT_DIM + h * DK;
    const float* al  = a_l + h * DK;
    const float* ar  = a_r + h * DK;
    float sl = 0.f, sr = 0.f;
    #pragma unroll
    for (int d = lane; d < DK; d += 32) {
        float v = row[d];
        sl += v * al[d];
        sr += v * ar[d];
    }
    #pragma unroll
    for (int o = 16; o; o >>= 1) {
        sl += __shfl_xor_sync(0xffffffffu, sl, o);
        sr += __shfl_xor_sync(0xffffffffu, sr, o);
    }
    if (lane == 0) {
        g_sl[i * HEADS + h] = sl;
        g_sr[i * HEADS + h] = sr;
    }
}

// ---------------------------------------------------------------------------
// Kernel 3: fused masked-softmax attention + aggregation + ELU
// CTA = 32 i-rows x all 4 heads; loops over all j in tiles of 32.
// ---------------------------------------------------------------------------
#define SMEM_FLOATS (BJ * OUT_DIM + BJ * WROW + 3 * 128)
#define SMEM_BYTES  (SMEM_FLOATS * 4 + BI * AROW * 4)

__global__ __launch_bounds__(512, 1) void gat_fused(const int* __restrict__ A,
                                                    float* __restrict__ out) {
    extern __shared__ float smem[];
    float* Wh_s = smem;                    // BJ*512 floats (64 KB)
    float* w_s  = Wh_s + BJ * OUT_DIM;     // BJ*WROW floats: w_s[j][h*32+i], padded
    float* sl_s = w_s + BJ * WROW;         // 128: [i*4+h]
    float* sr_s = sl_s + 128;              // 128: [j*4+h]
    float* z_s  = sr_s + 128;              // 128: [i*4+h]
    int*   a_s  = (int*)(z_s + 128);       // BI x AROW

    const int t  = threadIdx.x;
    const int i0 = blockIdx.x * BI;

    // phase-C (aggregation) ids: t = itC*128 + hC*32 + dg
    const int itC = t >> 7;
    const int hC  = (t >> 5) & 3;
    const int dg  = t & 31;
    // phase-B (score) ids: t = jB*16 + hB*4 + itB
    const int jB  = t >> 4;
    const int hB  = (t >> 2) & 3;
    const int itB = t & 3;

    if (t < 128) sl_s[t] = g_sl[i0 * HEADS + t];
    __syncthreads();

    float slr[8];
    #pragma unroll
    for (int ii = 0; ii < 8; ++ii) slr[ii] = sl_s[(itB * 8 + ii) * 4 + hB];

    ull acc[4][4];  // [i-pair][d]; each ull = packed fp32 pair over (i, i+1)
    #pragma unroll
    for (int p = 0; p < 4; ++p)
        #pragma unroll
        for (int d = 0; d < 4; ++d) acc[p][d] = 0ull;
    float zp[8];
    #pragma unroll
    for (int ii = 0; ii < 8; ++ii) zp[ii] = 0.f;

    for (int j0 = 0; j0 < N_NODES; j0 += BJ) {
        __syncthreads();
        // --- cooperative loads: Wh tile (float4), A mask tile, sr tile ---
        {
            const float4* src = (const float4*)(g_Wh + (size_t)j0 * OUT_DIM);
            float4* dst = (float4*)Wh_s;
            #pragma unroll
            for (int k = 0; k < 8; ++k) dst[t + k * 512] = src[t + k * 512];
        }
        #pragma unroll
        for (int k = 0; k < 2; ++k) {
            int idx = t + k * 512;
            int r = idx >> 5, c = idx & 31;
            a_s[r * AROW + c] = A[(size_t)(i0 + r) * N_NODES + j0 + c];
        }
        if (t < 128) sr_s[t] = g_sr[j0 * HEADS + t];
        __syncthreads();

        // --- phase B: w = mask ? exp(lrelu(sl_i + sr_j)) : 0 ---
        {
            float srv = sr_s[jB * 4 + hB];
            float wv[8];
            #pragma unroll
            for (int ii = 0; ii < 8; ++ii) {
                int i = itB * 8 + ii;
                bool m = (a_s[i * AROW + jB] != 0) || (i0 + i == j0 + jB);
                float e = slr[ii] + srv;
                e = fmaxf(e, 0.2f * e);              // leaky_relu
                float w = m ? __expf(e) : 0.f;
                wv[ii] = w;
                zp[ii] += w;                         // running Z partial (this j-slot)
            }
            float* wp = w_s + jB * WROW + hB * 32 + itB * 8;
            *(float4*)(wp + 0) = make_float4(wv[0], wv[1], wv[2], wv[3]);
            *(float4*)(wp + 4) = make_float4(wv[4], wv[5], wv[6], wv[7]);
        }
        __syncthreads();

        // --- phase C: acc[i,h,d] += w[i,h,j] * Wh[j,h,d] (packed f32x2) ---
        {
            const float* vbase = Wh_s + hC * DK + dg * 4;
            const float* wbase = w_s + hC * 32 + itC * 8;
            #pragma unroll 8
            for (int j = 0; j < BJ; ++j) {
                float4 v = *(const float4*)(vbase + (size_t)j * OUT_DIM);
                ulonglong2 wa = *(const ulonglong2*)(wbase + j * WROW);
                ulonglong2 wb = *(const ulonglong2*)(wbase + j * WROW + 4);
                ull w4[4] = { wa.x, wa.y, wb.x, wb.y };
                ull vv[4] = { pk2(v.x), pk2(v.y), pk2(v.z), pk2(v.w) };
                #pragma unroll
                for (int p = 0; p < 4; ++p)
                    #pragma unroll
                    for (int d = 0; d < 4; ++d)
                        fma2(acc[p][d], w4[p], vv[d]);
            }
        }
    }

    // --- final Z reduction: zp held per (j-slot, h, itB); reduce over 32 j-slots ---
    __syncthreads();
    {
        float* wp = w_s + jB * WROW + hB * 32 + itB * 8;
        *(float4*)(wp + 0) = make_float4(zp[0], zp[1], zp[2], zp[3]);
        *(float4*)(wp + 4) = make_float4(zp[4], zp[5], zp[6], zp[7]);
    }
    __syncthreads();
    {
        int pr = t >> 2, js = t & 3;
        int iD = pr & 31, hD = pr >> 5;
        float zsum = 0.f;
        #pragma unroll
        for (int jj = 0; jj < 8; ++jj) {
            int j = js + jj * 4;
            zsum += w_s[j * WROW + hD * 32 + iD];
        }
        zsum += __shfl_xor_sync(0xffffffffu, zsum, 1);
        zsum += __shfl_xor_sync(0xffffffffu, zsum, 2);
        if (js == 0) z_s[iD * 4 + hD] = zsum;
    }
    __syncthreads();

    // --- epilogue: normalize + ELU, vectorized stores ---
    #pragma unroll
    for (int p = 0; p < 4; ++p) {
        int iA = itC * 8 + 2 * p;
        float invA = 1.f / z_s[iA * 4 + hC];
        float invB = 1.f / z_s[(iA + 1) * 4 + hC];
        float2 d0 = up2(acc[p][0]), d1 = up2(acc[p][1]);
        float2 d2 = up2(acc[p][2]), d3 = up2(acc[p][3]);
        float4 oA = make_float4(elu1(d0.x * invA), elu1(d1.x * invA),
                                elu1(d2.x * invA), elu1(d3.x * invA));
        float4 oB = make_float4(elu1(d0.y * invB), elu1(d1.y * invB),
                                elu1(d2.y * invB), elu1(d3.y * invB));
        size_t base = (size_t)(i0 + iA) * OUT_DIM + hC * DK + dg * 4;
        *(float4*)(out + base)           = oA;
        *(float4*)(out + base + OUT_DIM) = oB;
    }
}

// ---------------------------------------------------------------------------
extern "C" void kernel_launch(void* const* d_in, const int* in_sizes, int n_in,
                              void* d_out, int out_size) {
    const float* H   = (const float*)d_in[0];
    const int*   A   = (const int*)d_in[1];
    const float* W   = (const float*)d_in[2];
    const float* a_l = (const float*)d_in[3];
    const float* a_r = (const float*)d_in[4];
    float* out = (float*)d_out;

    cudaFuncSetAttribute(gat_fused, cudaFuncAttributeMaxDynamicSharedMemorySize,
                         SMEM_BYTES);

    gemm_wh<<<dim3(OUT_DIM / 64, N_NODES / 64), 256>>>(H, W);
    slsr_kernel<<<N_NODES, 128>>>(a_l, a_r);
    gat_fused<<<N_NODES / BI, 512, SMEM_BYTES>>>(A, out);
}

// round 13
// speedup vs baseline: 2.3648x; 2.3648x over previous
#include <cuda_runtime.h>
#include <cstdint>
#include <cstddef>

#define N_NODES 4096
#define IN_DIM  512
#define OUT_DIM 512
#define HEADS   4
#define DK      128
#define BJT     64
#define NTILES  (N_NODES / BJT)
#define LOG2E   1.4426950408889634f

typedef unsigned long long ull;

// ---------------- device scratch ----------------
__device__ float g_Wh[N_NODES * OUT_DIM];
__device__ float g_Vtp[OUT_DIM * N_NODES];      // [c][j-permuted], tf32-rounded fp32
__device__ float g_sl[HEADS * N_NODES];         // head-major, pre-scaled by log2(e)
__device__ float g_srp[HEADS * N_NODES];        // head-major, j-permuted, pre-scaled
__device__ ull   g_Abits[N_NODES * (N_NODES / 64)]; // 64 j-bits per ull, self-loops baked

// ---------------- helpers ----------------
__device__ __forceinline__ uint32_t smem_u32(const void* p) {
    uint32_t a;
    asm("{ .reg .u64 t; cvta.to.shared.u64 t, %1; cvt.u32.u64 %0, t; }" : "=r"(a) : "l"(p));
    return a;
}
__device__ __forceinline__ ull pk2(float x) { ull r; asm("mov.b64 %0, {%1, %1};" : "=l"(r) : "f"(x)); return r; }
__device__ __forceinline__ void fma2(ull &a, ull b, ull c) {
    asm("fma.rn.f32x2 %0, %1, %2, %0;" : "+l"(a) : "l"(b), "l"(c));
}
__device__ __forceinline__ float2 up2(ull a) { float2 f; asm("mov.b64 {%0, %1}, %2;" : "=f"(f.x), "=f"(f.y) : "l"(a)); return f; }
__device__ __forceinline__ float elu1(float x) { return x > 0.f ? x : (__expf(x) - 1.f); }
__device__ __forceinline__ float ex2(float x) { float y; asm("ex2.approx.f32 %0, %1;" : "=f"(y) : "f"(x)); return y; }
__device__ __forceinline__ uint32_t tf32r(float w) {
    uint32_t u; asm("cvt.rna.tf32.f32 %0, %1;" : "=r"(u) : "f"(w)); return u;
}
// j-permutation within blocks of 8: position p holds source j = ((p>>1)&3) | ((p&1)<<2)
__device__ __forceinline__ int jperm_pos(int j) {           // source j -> stored position
    return (j & ~7) | ((j & 3) << 1) | ((j >> 2) & 1);
}

#define MMA_TF32(c, a, b0, b1)                                                   \
    asm("mma.sync.aligned.m16n8k8.row.col.f32.tf32.tf32.f32 "                    \
        "{%0,%1,%2,%3}, {%4,%5,%6,%7}, {%8,%9}, {%0,%1,%2,%3};"                  \
        : "+f"((c)[0]), "+f"((c)[1]), "+f"((c)[2]), "+f"((c)[3])                 \
        : "r"((a)[0]), "r"((a)[1]), "r"((a)[2]), "r"((a)[3]), "r"(b0), "r"(b1))

// ---------------------------------------------------------------------------
// Kernel 1: Wh = H @ W  (fp32, f32x2 packed FMA)
// ---------------------------------------------------------------------------
__global__ __launch_bounds__(256) void gemm_wh(const float* __restrict__ H,
                                               const float* __restrict__ W) {
    __shared__ float As[16][64];
    __shared__ float Bs[16][64];
    const int t  = threadIdx.x;
    const int m0 = blockIdx.y * 64;
    const int n0 = blockIdx.x * 64;
    const int lm = t >> 2, lkq = t & 3;
    const int lk = t >> 4, lnq = t & 15;
    const int ty = t >> 4, tx = t & 15;
    const int row0 = ty * 4, col0 = tx * 4;

    ull acc[4][2];
    #pragma unroll
    for (int r = 0; r < 4; ++r) { acc[r][0] = 0ull; acc[r][1] = 0ull; }

    for (int k0 = 0; k0 < IN_DIM; k0 += 16) {
        __syncthreads();
        float4 ha = *(const float4*)(H + (size_t)(m0 + lm) * IN_DIM + k0 + lkq * 4);
        As[lkq * 4 + 0][lm] = ha.x;
        As[lkq * 4 + 1][lm] = ha.y;
        As[lkq * 4 + 2][lm] = ha.z;
        As[lkq * 4 + 3][lm] = ha.w;
        *(float4*)&Bs[lk][lnq * 4] =
            *(const float4*)(W + (size_t)(k0 + lk) * OUT_DIM + n0 + lnq * 4);
        __syncthreads();
        #pragma unroll
        for (int k = 0; k < 16; ++k) {
            float4 av = *(const float4*)&As[k][row0];
            ulonglong2 bb = *(const ulonglong2*)&Bs[k][col0];
            ull am[4] = { pk2(av.x), pk2(av.y), pk2(av.z), pk2(av.w) };
            #pragma unroll
            for (int r = 0; r < 4; ++r) {
                fma2(acc[r][0], am[r], bb.x);
                fma2(acc[r][1], am[r], bb.y);
            }
        }
    }
    #pragma unroll
    for (int r = 0; r < 4; ++r) {
        float2 lo = up2(acc[r][0]);
        float2 hi = up2(acc[r][1]);
        *(float4*)(g_Wh + (size_t)(m0 + row0 + r) * OUT_DIM + n0 + col0) =
            make_float4(lo.x, lo.y, hi.x, hi.y);
    }
}

// ---------------------------------------------------------------------------
// Kernel 2: sl/sr (head-major, pre-scaled by log2e, sr j-permuted)
// ---------------------------------------------------------------------------
__global__ __launch_bounds__(128) void slsr_kernel(const float* __restrict__ a_l,
                                                   const float* __restrict__ a_r) {
    const int i = blockIdx.x;
    const int h = threadIdx.x >> 5;
    const int lane = threadIdx.x & 31;
    const float* row = g_Wh + (size_t)i * OUT_DIM + h * DK;
    const float* al = a_l + h * DK;
    const float* ar = a_r + h * DK;
    float sl = 0.f, sr = 0.f;
    #pragma unroll
    for (int d = lane; d < DK; d += 32) {
        float v = row[d];
        sl += v * al[d];
        sr += v * ar[d];
    }
    #pragma unroll
    for (int o = 16; o; o >>= 1) {
        sl += __shfl_xor_sync(0xffffffffu, sl, o);
        sr += __shfl_xor_sync(0xffffffffu, sr, o);
    }
    if (lane == 0) {
        g_sl[h * N_NODES + i] = sl * LOG2E;
        g_srp[h * N_NODES + jperm_pos(i)] = sr * LOG2E;
    }
}

// ---------------------------------------------------------------------------
// Kernel 3: pack adjacency (+self-loop) into 64-bit masks
// ---------------------------------------------------------------------------
__global__ __launch_bounds__(256) void pack_A(const int* __restrict__ A) {
    const int gid = blockIdx.x * 256 + threadIdx.x;
    const int w = gid >> 5, lane = gid & 31;   // w: 32-bit word id, 128 per row
    const int i = w >> 7;
    const int j = (w & 127) * 32 + lane;
    int a = A[(size_t)i * N_NODES + j];
    unsigned word = __ballot_sync(0xffffffffu, a != 0 || i == j);
    if (lane == 0) ((unsigned*)g_Abits)[w] = word;
}

// ---------------------------------------------------------------------------
// Kernel 4: Wh -> Vtp  (transpose, j-permute, tf32 round)
// ---------------------------------------------------------------------------
__global__ __launch_bounds__(1024) void convert_vtp() {
    __shared__ float ts[32][33];
    const int j0 = blockIdx.x * 32, c0 = blockIdx.y * 32;
    const int tx = threadIdx.x, ty = threadIdx.y;
    ts[ty][tx] = g_Wh[(size_t)(j0 + ty) * OUT_DIM + c0 + tx];
    __syncthreads();
    int p8 = tx & 7;
    int jsrc = (tx & ~7) | (p8 >> 1) | ((p8 & 1) << 2);
    uint32_t u = tf32r(ts[jsrc][ty]);
    g_Vtp[(size_t)(c0 + ty) * N_NODES + j0 + tx] = __uint_as_float(u);
}

// ---------------------------------------------------------------------------
// Kernel 5: fused masked-softmax attention via mma.sync tf32
// CTA = 128 i-rows x 1 head; 8 warps = 4 rowgroups(32 rows) x 2 K-halves(32 j)
// ---------------------------------------------------------------------------
#define VROW      288
#define VBUF_SZ   (128 * VROW)            // 36864
#define OFF_SR    (2 * VBUF_SZ)           // 73728
#define OFF_Z     (OFF_SR + 512)          // 74240
#define SMEM_TOT  (OFF_Z + 512)           // 74752
#define MROW      544
#define MERGE_RG  (32 * MROW)             // 17408 (reuses V buffers)

__device__ __forceinline__ void stage_tile(uint32_t sb, int h, int tile, int buf, int t) {
    const float* srcb = g_Vtp + (size_t)(h * DK) * N_NODES + tile * BJT;
    uint32_t vd = sb + buf * VBUF_SZ;
    #pragma unroll
    for (int p = 0; p < 8; ++p) {
        int idx = p * 256 + t;
        int c = idx >> 4, ch = idx & 15;
        uint32_t d = vd + c * VROW + ch * 16;
        const float* s = srcb + (size_t)c * N_NODES + ch * 4;
        asm volatile("cp.async.cg.shared.global [%0], [%1], 16;" :: "r"(d), "l"(s) : "memory");
    }
    if (t < 16) {
        uint32_t d = sb + OFF_SR + buf * 256 + t * 16;
        const float* s = g_srp + h * N_NODES + tile * BJT + t * 4;
        asm volatile("cp.async.cg.shared.global [%0], [%1], 16;" :: "r"(d), "l"(s) : "memory");
    }
}

__global__ __launch_bounds__(256, 1) void gat_fused(float* __restrict__ out) {
    extern __shared__ char sm[];
    const uint32_t sb = smem_u32(sm);
    const int t = threadIdx.x, w = t >> 5, lane = t & 31;
    const int g = lane >> 2, tg = lane & 3;
    const int rg = w & 3, kh = w >> 2;
    const int h = blockIdx.x & 3;
    const int i0 = (blockIdx.x >> 2) * 128;

    if (t < 128) ((float*)(sm + OFF_Z))[t] = 0.f;

    int r[4];
    #pragma unroll
    for (int i = 0; i < 4; ++i) r[i] = rg * 32 + g + 8 * i;

    float sl[4];
    const ull* ab[4];
    #pragma unroll
    for (int i = 0; i < 4; ++i) {
        sl[i] = g_sl[h * N_NODES + i0 + r[i]];
        ab[i] = g_Abits + (size_t)(i0 + r[i]) * NTILES;
    }

    float acc[128];
    #pragma unroll
    for (int q = 0; q < 128; ++q) acc[q] = 0.f;
    float z[4] = {0.f, 0.f, 0.f, 0.f};

    stage_tile(sb, h, 0, 0, t);
    asm volatile("cp.async.commit_group;" ::: "memory");

    // sr offset selects this warp's K-half (kh*32 floats = kh*128 bytes)
    const int srOff0 = OFF_SR + kh * 128 + tg * 8;
    const int vbOff0 = g * VROW + kh * 128 + tg * 8;

    for (int tile = 0; tile < NTILES; ++tile) {
        const int buf = tile & 1;
        if (tile + 1 < NTILES) {
            stage_tile(sb, h, tile + 1, buf ^ 1, t);
            asm volatile("cp.async.commit_group;" ::: "memory");
            asm volatile("cp.async.wait_group 1;" ::: "memory");
        } else {
            asm volatile("cp.async.wait_group 0;" ::: "memory");
        }
        __syncthreads();

        unsigned mh[4];
        #pragma unroll
        for (int i = 0; i < 4; ++i)
            mh[i] = (unsigned)(__ldg(ab[i] + tile) >> (kh * 32));

        const char* srP = sm + srOff0 + buf * 256;
        const char* vbP = sm + vbOff0 + buf * VBUF_SZ;

        #pragma unroll
        for (int ch = 0; ch < 4; ++ch) {
            float2 srp = *(const float2*)(srP + ch * 32);
            uint32_t af[2][4];
            #pragma unroll
            for (int i = 0; i < 4; ++i) {
                float x0 = sl[i] + srp.x;
                float x1 = sl[i] + srp.y;
                x0 = fmaxf(x0, 0.2f * x0);
                x1 = fmaxf(x1, 0.2f * x1);
                float w0 = ex2(x0), w1 = ex2(x1);
                w0 = ((mh[i] >> (ch * 8 + tg)) & 1u) ? w0 : 0.f;
                w1 = ((mh[i] >> (ch * 8 + tg + 4)) & 1u) ? w1 : 0.f;
                uint32_t u0 = tf32r(w0), u1 = tf32r(w1);
                z[i] += __uint_as_float(u0) + __uint_as_float(u1);
                af[i >> 1][(i & 1)]     = u0;
                af[i >> 1][2 + (i & 1)] = u1;
            }
            #pragma unroll
            for (int nt = 0; nt < 16; ++nt) {
                uint2 bv = *(const uint2*)(vbP + nt * (8 * VROW) + ch * 32);
                MMA_TF32(&acc[nt * 4],      af[0], bv.x, bv.y);
                MMA_TF32(&acc[64 + nt * 4], af[1], bv.x, bv.y);
            }
        }
        __syncthreads();
    }

    // -------- Z reduction (across tg quad, both K-halves via smem atomics) ----
    #pragma unroll
    for (int i = 0; i < 4; ++i) {
        z[i] += __shfl_xor_sync(0xffffffffu, z[i], 1);
        z[i] += __shfl_xor_sync(0xffffffffu, z[i], 2);
    }
    if (tg == 0) {
        #pragma unroll
        for (int i = 0; i < 4; ++i)
            atomicAdd((float*)(sm + OFF_Z) + r[i], z[i]);
    }
    __syncthreads();

    // -------- merge K-halves: kh=1 stores, kh=0 adds + epilogue ---------------
    if (kh == 1) {
        #pragma unroll
        for (int rb = 0; rb < 2; ++rb) {
            char* m0 = sm + rg * MERGE_RG + (g + 16 * rb) * MROW + tg * 8;
            char* m1 = m0 + 8 * MROW;
            #pragma unroll
            for (int nt = 0; nt < 16; ++nt) {
                *(float2*)(m0 + nt * 32) =
                    make_float2(acc[rb * 64 + nt * 4], acc[rb * 64 + nt * 4 + 1]);
                *(float2*)(m1 + nt * 32) =
                    make_float2(acc[rb * 64 + nt * 4 + 2], acc[rb * 64 + nt * 4 + 3]);
            }
        }
    }
    __syncthreads();
    if (kh == 0) {
        float inv[4];
        #pragma unroll
        for (int i = 0; i < 4; ++i)
            inv[i] = 1.f / ((float*)(sm + OFF_Z))[r[i]];
        #pragma unroll
        for (int rb = 0; rb < 2; ++rb) {
            const char* m0 = sm + rg * MERGE_RG + (g + 16 * rb) * MROW + tg * 8;
            const char* m1 = m0 + 8 * MROW;
            float* op = out + (size_t)(i0 + rg * 32 + g + 16 * rb) * OUT_DIM +
                        h * DK + tg * 2;
            #pragma unroll
            for (int nt = 0; nt < 16; ++nt) {
                float2 pa = *(const float2*)(m0 + nt * 32);
                float2 pb = *(const float2*)(m1 + nt * 32);
                float d0 = acc[rb * 64 + nt * 4]     + pa.x;
                float d1 = acc[rb * 64 + nt * 4 + 1] + pa.y;
                float d2 = acc[rb * 64 + nt * 4 + 2] + pb.x;
                float d3 = acc[rb * 64 + nt * 4 + 3] + pb.y;
                float2 oA = make_float2(elu1(d0 * inv[2 * rb]), elu1(d1 * inv[2 * rb]));
                float2 oB = make_float2(elu1(d2 * inv[2 * rb + 1]), elu1(d3 * inv[2 * rb + 1]));
                *(float2*)(op + nt * 8)                = oA;
                *(float2*)(op + nt * 8 + 8 * OUT_DIM)  = oB;
            }
        }
    }
}

// ---------------------------------------------------------------------------
extern "C" void kernel_launch(void* const* d_in, const int* in_sizes, int n_in,
                              void* d_out, int out_size) {
    const float* H   = (const float*)d_in[0];
    const int*   A   = (const int*)d_in[1];
    const float* W   = (const float*)d_in[2];
    const float* a_l = (const float*)d_in[3];
    const float* a_r = (const float*)d_in[4];
    float* out = (float*)d_out;

    cudaFuncSetAttribute(gat_fused, cudaFuncAttributeMaxDynamicSharedMemorySize, SMEM_TOT);

    pack_A<<<(N_NODES / 16) * (N_NODES / 16), 256>>>(A);   // one thread per element
    gemm_wh<<<dim3(OUT_DIM / 64, N_NODES / 64), 256>>>(H, W);
    slsr_kernel<<<N_NODES, 128>>>(a_l, a_r);
    convert_vtp<<<dim3(N_NODES / 32, OUT_DIM / 32), dim3(32, 32)>>>();
    gat_fused<<<(N_NODES / 128) * HEADS, 256, SMEM_TOT>>>(out);
}